// round 9
// baseline (speedup 1.0000x reference)
#include <cuda_runtime.h>
#include <cstdint>

__constant__ int c_starts[17] = {0, 4, 6, 8, 12, 16, 19, 22, 24, 28, 30, 36, 38, 41, 44, 47, 50};

#define MAX_BC 4096
__device__ unsigned g_inter[MAX_BC];
__device__ unsigned g_pred[MAX_BC];
__device__ unsigned g_gt[MAX_BC];
__device__ unsigned g_done;   // zero-initialized; reset by last block each run

// ---------------- TMA / mbarrier helpers ----------------
static __device__ __forceinline__ uint32_t smem_u32(const void* p) {
    return (uint32_t)__cvta_generic_to_shared(p);
}
static __device__ __forceinline__ void mbar_init(uint32_t a, uint32_t cnt) {
    asm volatile("mbarrier.init.shared.b64 [%0], %1;" :: "r"(a), "r"(cnt) : "memory");
}
static __device__ __forceinline__ void mbar_expect_tx(uint32_t a, uint32_t bytes) {
    asm volatile("mbarrier.arrive.expect_tx.shared.b64 _, [%0], %1;" :: "r"(a), "r"(bytes) : "memory");
}
static __device__ __forceinline__ void mbar_arrive(uint32_t a) {
    asm volatile("mbarrier.arrive.shared.b64 _, [%0];" :: "r"(a) : "memory");
}
static __device__ __forceinline__ void mbar_wait(uint32_t a, uint32_t parity) {
    asm volatile(
        "{\n\t.reg .pred P;\n\t"
        "WL%=:\n\t"
        "mbarrier.try_wait.parity.acquire.cta.shared::cta.b64 P, [%0], %1, 0x989680;\n\t"
        "@P bra WD%=;\n\t"
        "bra WL%=;\n\t"
        "WD%=:\n\t}"
        :: "r"(a), "r"(parity) : "memory");
}
static __device__ __forceinline__ void bulk_g2s(uint32_t dst, const void* src,
                                                uint32_t bytes, uint32_t mbar) {
    asm volatile("cp.async.bulk.shared::cta.global.mbarrier::complete_tx::bytes [%0], [%1], %2, [%3];"
                 :: "r"(dst), "l"(src), "r"(bytes), "r"(mbar) : "memory");
}
static __device__ __forceinline__ void fence_async_shared() {
    asm volatile("fence.proxy.async.shared::cta;" ::: "memory");
}

// ---------------- fast path constants ----------------
constexpr int TPB_F      = 288;               // 8 consumer warps + 1 producer warp
constexpr int CONSUMERS  = 256;
constexpr int TILE_PTS   = 1024;              // points per stage
constexpr int TILE_B     = TILE_PTS * 4;      // 4096 B per staged row
constexpr int MAXROWS    = 7;                 // up to 6 logit rows + 1 targets row
constexpr int STAGE_B    = MAXROWS * TILE_B;  // 28672 B per stage
constexpr int RING       = 3;                 // stages in flight
constexpr int NSTAGES    = 4;                 // stages processed per block
constexpr int SPAN       = TILE_PTS * NSTAGES;// 4096 points per block
constexpr int SMEM_DYN   = RING * STAGE_B;    // 86016 B

template <int W>
__device__ __forceinline__ void tma_issue(const float* __restrict__ l0,
                                          const int* __restrict__ tb,
                                          int n0s, uint32_t sb, uint32_t mb, int N)
{
    mbar_expect_tx(mb, (W + 1) * TILE_B);
#pragma unroll
    for (int j = 0; j < W; ++j)
        bulk_g2s(sb + j * TILE_B, l0 + (size_t)j * N + n0s, TILE_B, mb);
    bulk_g2s(sb + W * TILE_B, tb + n0s, TILE_B, mb);
}

// Packed 64-bit accumulators: 6 bins x 10 bits; per-warp bin sums <= 32*16 = 512 < 1023.
template <int W>
__device__ __forceinline__ void ws_body(const float* __restrict__ l0,
                                        const int* __restrict__ tb,
                                        float* __restrict__ pb,
                                        int start, int N, int b, int C, int n0,
                                        const char* sm, uint32_t sm_a,
                                        uint32_t fb, uint32_t eb,
                                        unsigned* s_pred, unsigned* s_inter, unsigned* s_gt)
{
    const int tid = threadIdx.x;
    const int wid = tid >> 5;

    if (wid == 8) {
        // ---- producer warp: keep RING stages in flight, no block syncs ----
        if ((tid & 31) == 0) {
            int slot = 0, ph = 1;                       // init phase 1: first waits pass
#pragma unroll
            for (int s = 0; s < NSTAGES; ++s) {
                mbar_wait(eb + slot * 8, (uint32_t)ph);
                fence_async_shared();                   // order consumer reads before refill
                tma_issue<W>(l0, tb, n0 + s * TILE_PTS, sm_a + slot * STAGE_B, fb + slot * 8, N);
                if (++slot == RING) { slot = 0; ph ^= 1; }
            }
        }
    } else {
        // ---- consumer warps ----
        unsigned long long acc_p = 0ull, acc_i = 0ull, acc_g = 0ull;
        int slot = 0, ph = 0;
#pragma unroll
        for (int s = 0; s < NSTAGES; ++s) {
            mbar_wait(fb + slot * 8, (uint32_t)ph);
            const char* sb = sm + slot * STAGE_B;
            const int off = tid * 16;

            float4 best = *reinterpret_cast<const float4*>(sb + off);
            int bc0 = 0, bc1 = 0, bc2 = 0, bc3 = 0;
#pragma unroll
            for (int j = 1; j < W; ++j) {
                const float4 v = *reinterpret_cast<const float4*>(sb + j * TILE_B + off);
                if (v.x > best.x) { best.x = v.x; bc0 = j; }  // strict > keeps first index on ties
                if (v.y > best.y) { best.y = v.y; bc1 = j; }
                if (v.z > best.z) { best.z = v.z; bc2 = j; }
                if (v.w > best.w) { best.w = v.w; bc3 = j; }
            }
            const int4 t4 = *reinterpret_cast<const int4*>(sb + W * TILE_B + off);

            __syncwarp();                                  // warp-wide reads done
            if ((tid & 31) == 0) mbar_arrive(eb + slot * 8);  // release the buffer early

            const int n = n0 + s * TILE_PTS + tid * 4;
            const int bcs[4] = {bc0, bc1, bc2, bc3};
            const int tg[4]  = {t4.x, t4.y, t4.z, t4.w};
#pragma unroll
            for (int e = 0; e < 4; ++e) {
                const unsigned bt = (unsigned)(tg[e] - start);
                const unsigned long long one = 1ull << (bcs[e] * 10);
                acc_p += one;
                if (bt == (unsigned)bcs[e]) acc_i += one;            // intersection
                if (bt < (unsigned)W) acc_g += 1ull << (bt * 10);    // in-range gt
                pb[n + e] = (float)(bcs[e] + start);                 // pb may be 4B-offset
            }
            if (++slot == RING) { slot = 0; ph ^= 1; }
        }

        // warp-level reduction of packed accumulators
#pragma unroll
        for (int o = 16; o; o >>= 1) {
            acc_p += __shfl_down_sync(0xFFFFFFFFu, acc_p, o);
            acc_i += __shfl_down_sync(0xFFFFFFFFu, acc_i, o);
            acc_g += __shfl_down_sync(0xFFFFFFFFu, acc_g, o);
        }
        if ((tid & 31) == 0) {
#pragma unroll
            for (int j = 0; j < W; ++j) {
                const unsigned cp = (unsigned)((acc_p >> (10 * j)) & 1023u);
                const unsigned ci = (unsigned)((acc_i >> (10 * j)) & 1023u);
                const unsigned cg = (unsigned)((acc_g >> (10 * j)) & 1023u);
                if (cp) atomicAdd(&s_pred[j], cp);
                if (ci) atomicAdd(&s_inter[j], ci);
                if (cg) atomicAdd(&s_gt[j], cg);
            }
        }
    }
    __syncthreads();
    if (tid < W) {
        const int g = b * C + start + tid;
        const unsigned sp = s_pred[tid], si = s_inter[tid], sg = s_gt[tid];
        if (sp) atomicAdd(&g_pred[g], sp);
        if (si) atomicAdd(&g_inter[g], si);
        if (sg) atomicAdd(&g_gt[g], sg);
    }
}

__global__ void __launch_bounds__(TPB_F)
seg_hist_ws(const float* __restrict__ logits,
            const int* __restrict__ targets,
            const int* __restrict__ labels,
            float* __restrict__ pred_out,
            float* __restrict__ mean_out,
            int C, int N, int B, int total_blocks)
{
    extern __shared__ __align__(128) char sm[];
    __shared__ __align__(8) unsigned long long full_b[RING], empty_b[RING];
    __shared__ unsigned s_pred[8], s_inter[8], s_gt[8];

    const int tid = threadIdx.x;
    if (tid < 8) { s_pred[tid] = 0u; s_inter[tid] = 0u; s_gt[tid] = 0u; }
    const uint32_t fb = smem_u32(full_b);
    const uint32_t eb = smem_u32(empty_b);
    const uint32_t sm_a = smem_u32(sm);
    if (tid == 0) {
#pragma unroll
        for (int r = 0; r < RING; ++r) { mbar_init(fb + r * 8, 1); mbar_init(eb + r * 8, 8); }
        fence_async_shared();
    }
    __syncthreads();

    const int b = blockIdx.y;
    int cls = labels[b];
    cls = min(max(cls, 0), 15);
    const int start = c_starts[cls];
    const int width = c_starts[cls + 1] - start;

    const float* l0 = logits + ((size_t)b * C + start) * N;
    const int* tb = targets + (size_t)b * N;
    float* pb = pred_out + (size_t)b * N;
    const int n0 = blockIdx.x * SPAN;

    switch (width) {
        case 2: ws_body<2>(l0, tb, pb, start, N, b, C, n0, sm, sm_a, fb, eb, s_pred, s_inter, s_gt); break;
        case 3: ws_body<3>(l0, tb, pb, start, N, b, C, n0, sm, sm_a, fb, eb, s_pred, s_inter, s_gt); break;
        case 4: ws_body<4>(l0, tb, pb, start, N, b, C, n0, sm, sm_a, fb, eb, s_pred, s_inter, s_gt); break;
        default: ws_body<6>(l0, tb, pb, start, N, b, C, n0, sm, sm_a, fb, eb, s_pred, s_inter, s_gt); break;
    }

    // ---- last-block finalize (fused tail) ----
    __shared__ unsigned s_last;
    if (tid == 0) {
        __threadfence();
        s_last = (atomicAdd(&g_done, 1u) == (unsigned)(total_blocks - 1)) ? 1u : 0u;
    }
    __syncthreads();
    if (!s_last) return;

    __shared__ float s_iou[64];
    float v = 0.0f;
    if (tid < B) {
        int cl = labels[tid];
        cl = min(max(cl, 0), 15);
        const int st = c_starts[cl];
        const int wd = c_starts[cl + 1] - st;

        unsigned ci[6], cp[6], cg[6];
#pragma unroll
        for (int j = 0; j < 6; ++j) {
            const int g = tid * C + st + min(j, wd - 1);
            ci[j] = g_inter[g]; cp[j] = g_pred[g]; cg[j] = g_gt[g];
        }
        float acc = 0.0f;
#pragma unroll
        for (int j = 0; j < 6; ++j) {
            if (j < wd) {
                const float inter = (float)ci[j];
                const float uni = (float)cp[j] + (float)cg[j] - inter;
                acc += (uni == 0.0f) ? 1.0f : (inter / fmaxf(uni, 1.0f));
            }
        }
        v = acc / (float)wd;
#pragma unroll
        for (int j = 0; j < 6; ++j) {
            if (j < wd) {
                const int g = tid * C + st + j;
                g_inter[g] = 0u; g_pred[g] = 0u; g_gt[g] = 0u;   // reset for next replay
            }
        }
    }
    if (tid < 64) s_iou[tid] = v;
    __syncthreads();
    if (tid == 0) {
        float total = 0.0f;
        for (int i = 0; i < B; i++) total += s_iou[i];
        if (mean_out) *mean_out = total / (float)B;
        g_done = 0u;
        __threadfence();
    }
}

// ---------------- fallback (generic sizes): separate kernels ----------------
template <int TPB>
__global__ void __launch_bounds__(TPB)
seg_hist_generic(const float* __restrict__ logits,
                 const int* __restrict__ targets,
                 const int* __restrict__ labels,
                 float* __restrict__ pred_out,
                 int C, int N)
{
    const int b = blockIdx.y;
    int cls = labels[b];
    cls = min(max(cls, 0), 15);
    const int start = c_starts[cls];
    const int width = c_starts[cls + 1] - start;

    __shared__ unsigned s_pred[8], s_gt[8], s_inter[8];
    if (threadIdx.x < 8) { s_pred[threadIdx.x] = 0u; s_gt[threadIdx.x] = 0u; s_inter[threadIdx.x] = 0u; }
    __syncthreads();

    const float* lb = logits + (size_t)b * C * N;
    const int* tb = targets + (size_t)b * N;
    float* pb = pred_out + (size_t)b * N;

    const int pts = (N + gridDim.x - 1) / gridDim.x;
    const int n0 = blockIdx.x * pts;
    const int n1 = min(n0 + pts, N);

    for (int n = n0 + threadIdx.x; n < n1; n += TPB) {
        float best = lb[(size_t)start * N + n];
        int bestc = 0;
        for (int j = 1; j < width; j++) {
            float v = lb[(size_t)(start + j) * N + n];
            if (v > best) { best = v; bestc = j; }
        }
        const unsigned bt = (unsigned)(tb[n] - start);
        atomicAdd(&s_pred[bestc], 1u);
        if (bt == (unsigned)bestc) atomicAdd(&s_inter[bestc], 1u);
        if (bt < (unsigned)width) atomicAdd(&s_gt[bt], 1u);
        pb[n] = (float)(bestc + start);
    }
    __syncthreads();
    if (threadIdx.x < width) {
        const int g = b * C + start + threadIdx.x;
        if (s_pred[threadIdx.x])  atomicAdd(&g_pred[g],  s_pred[threadIdx.x]);
        if (s_gt[threadIdx.x])    atomicAdd(&g_gt[g],    s_gt[threadIdx.x]);
        if (s_inter[threadIdx.x]) atomicAdd(&g_inter[g], s_inter[threadIdx.x]);
    }
}

__global__ void finalize_kernel(const int* __restrict__ labels,
                                float* __restrict__ mean_out,
                                int B, int C)
{
    __shared__ float s_iou[128];
    const int b = threadIdx.x;
    float v = 0.0f;
    if (b < B) {
        int cls = labels[b];
        cls = min(max(cls, 0), 15);
        const int start = c_starts[cls];
        const int end = c_starts[cls + 1];
        float acc = 0.0f;
        for (int p = start; p < end; p++) {
            const int g = b * C + p;
            const float inter = (float)g_inter[g];
            const float uni = (float)g_pred[g] + (float)g_gt[g] - inter;
            const float iou = (uni == 0.0f) ? 1.0f : (inter / fmaxf(uni, 1.0f));
            acc += iou;
            g_inter[g] = 0u; g_pred[g] = 0u; g_gt[g] = 0u;
        }
        v = acc / (float)(end - start);
    }
    if (b < 128) s_iou[b] = v;
    __syncthreads();
    if (threadIdx.x == 0) {
        float total = 0.0f;
        for (int i = 0; i < B; i++) total += s_iou[i];
        if (mean_out) *mean_out = total / (float)B;
    }
}

extern "C" void kernel_launch(void* const* d_in, const int* in_sizes, int n_in,
                              void* d_out, int out_size)
{
    // Identify inputs by element count (labels: B, targets: B*N, logits: B*C*N)
    int i_log = 0, i_lab = 0;
    for (int i = 0; i < 3; i++) {
        if (in_sizes[i] > in_sizes[i_log]) i_log = i;
        if (in_sizes[i] < in_sizes[i_lab]) i_lab = i;
    }
    const int i_tgt = 3 - i_log - i_lab;

    const float* logits  = (const float*)d_in[i_log];
    const int*   targets = (const int*)d_in[i_tgt];
    const int*   labels  = (const int*)d_in[i_lab];

    const int B  = in_sizes[i_lab];
    const int BN = in_sizes[i_tgt];
    const int N  = BN / B;
    const int C  = in_sizes[i_log] / BN;

    float* out = (float*)d_out;
    float* mean_out = nullptr;
    float* pred_out = nullptr;
    if (out_size >= BN + 1)      { mean_out = out; pred_out = out + 1; }
    else if (out_size == BN)     { pred_out = out; }
    else                         { mean_out = out; pred_out = out; }

    if (pred_out && (N % SPAN) == 0 && B <= 64 && B * C <= MAX_BC) {
        cudaFuncSetAttribute(seg_hist_ws, cudaFuncAttributeMaxDynamicSharedMemorySize, SMEM_DYN);
        dim3 grid(N / SPAN, B);
        const int total_blocks = (N / SPAN) * B;
        seg_hist_ws<<<grid, TPB_F, SMEM_DYN>>>(logits, targets, labels, pred_out,
                                               mean_out, C, N, B, total_blocks);
    } else {
        dim3 grid(32, B);
        seg_hist_generic<256><<<grid, 256>>>(logits, targets, labels, pred_out, C, N);
        finalize_kernel<<<1, 128>>>(labels, mean_out, B, C);
    }
}

// round 11
// speedup vs baseline: 1.2698x; 1.2698x over previous
#include <cuda_runtime.h>
#include <cstdint>

__constant__ int c_starts[17] = {0, 4, 6, 8, 12, 16, 19, 22, 24, 28, 30, 36, 38, 41, 44, 47, 50};

#define MAX_BC 4096
__device__ unsigned g_inter[MAX_BC];
__device__ unsigned g_pred[MAX_BC];
__device__ unsigned g_gt[MAX_BC];
__device__ unsigned g_done;   // zero-initialized; reset by last block each run

// ---------------- cp.async helpers ----------------
static __device__ __forceinline__ void cp_async16(uint32_t smem_dst, const void* gsrc) {
    asm volatile("cp.async.cg.shared.global [%0], [%1], 16;"
                 :: "r"(smem_dst), "l"(gsrc) : "memory");
}
static __device__ __forceinline__ void cp_commit() {
    asm volatile("cp.async.commit_group;" ::: "memory");
}
template <int K>
static __device__ __forceinline__ void cp_wait() {
    asm volatile("cp.async.wait_group %0;" :: "n"(K) : "memory");
}

// ---------------- fast path constants ----------------
constexpr int TPB_F   = 128;
constexpr int PTS_IT  = TPB_F * 4;            // 512 points per stage
constexpr int ROW_B   = PTS_IT * 4;           // 2048 B per staged row
constexpr int ROWS    = 7;                    // up to 6 logit rows + 1 targets row
constexpr int DEPTH   = 3;                    // cp.async pipeline depth (groups)
constexpr int ITERS   = 8;                    // stages per block
constexpr int SPAN    = PTS_IT * ITERS;       // 4096 points per block

// Per-thread private staging: thread t owns bytes [t*16, t*16+16) of each row.
// The issuing thread is the only consumer -> cp.async.wait_group is the only sync needed.
template <int W>
__device__ __forceinline__ void issue_stage(const float* __restrict__ l0,
                                            const int* __restrict__ tb,
                                            int s, uint32_t sm_a, int tid, int N)
{
    const uint32_t dst = sm_a + (s % DEPTH) * (ROWS * ROW_B) + tid * 16;
    const float* src = l0 + s * PTS_IT + tid * 4;
#pragma unroll
    for (int j = 0; j < W; ++j)
        cp_async16(dst + j * ROW_B, src + (size_t)j * N);
    cp_async16(dst + W * ROW_B, tb + s * PTS_IT + tid * 4);
    cp_commit();
}

// Packed 64-bit accumulators: 6 bins x 10 bits.
// Reduction stops at 16-lane partial sums (<= 16*32 = 512 < 1023) to avoid overflow.
template <int W>
__device__ __forceinline__ void fast_body(const float* __restrict__ l0,
                                          const int* __restrict__ tb,
                                          float* __restrict__ pb,
                                          int start, int N, int b, int C, int n0,
                                          char* sm, uint32_t sm_a,
                                          unsigned* s_pred, unsigned* s_inter, unsigned* s_gt)
{
    const int tid = threadIdx.x;

    // prologue: fill DEPTH-1 stages (pending groups = 2)
#pragma unroll
    for (int s = 0; s < DEPTH - 1; ++s)
        issue_stage<W>(l0, tb, s, sm_a, tid, N);

    unsigned long long acc_p = 0ull, acc_i = 0ull, acc_g = 0ull;

#pragma unroll
    for (int s = 0; s < ITERS; ++s) {
        cp_wait<DEPTH - 2>();                 // completes exactly stage s (see tail note)
        if (s + DEPTH - 1 < ITERS) {
            issue_stage<W>(l0, tb, s + DEPTH - 1, sm_a, tid, N);
        } else {
            cp_commit();                      // EMPTY group: keeps pending count uniform so
        }                                     // wait_group<1> always retires stage s, incl. tail

        const char* sb = sm + (s % DEPTH) * (ROWS * ROW_B) + tid * 16;
        float4 best = *reinterpret_cast<const float4*>(sb);
        int bc0 = 0, bc1 = 0, bc2 = 0, bc3 = 0;
#pragma unroll
        for (int j = 1; j < W; ++j) {
            const float4 v = *reinterpret_cast<const float4*>(sb + j * ROW_B);
            if (v.x > best.x) { best.x = v.x; bc0 = j; }  // strict > keeps first index on ties
            if (v.y > best.y) { best.y = v.y; bc1 = j; }
            if (v.z > best.z) { best.z = v.z; bc2 = j; }
            if (v.w > best.w) { best.w = v.w; bc3 = j; }
        }
        const int4 t4 = *reinterpret_cast<const int4*>(sb + W * ROW_B);

        const int n = n0 + s * PTS_IT + tid * 4;
        const int bcs[4] = {bc0, bc1, bc2, bc3};
        const int tg[4]  = {t4.x, t4.y, t4.z, t4.w};
#pragma unroll
        for (int e = 0; e < 4; ++e) {
            const unsigned bt = (unsigned)(tg[e] - start);
            const unsigned long long one = 1ull << (bcs[e] * 10);
            acc_p += one;
            if (bt == (unsigned)bcs[e]) acc_i += one;            // intersection
            if (bt < (unsigned)W) acc_g += 1ull << (bt * 10);    // in-range gt
            pb[n + e] = (float)(bcs[e] + start);                 // pb may be 4B-offset
        }
    }

    // partial warp reduction: stop at 16-lane sums to stay under the 10-bit field cap
#pragma unroll
    for (int o = 16; o >= 2; o >>= 1) {
        acc_p += __shfl_down_sync(0xFFFFFFFFu, acc_p, o);
        acc_i += __shfl_down_sync(0xFFFFFFFFu, acc_i, o);
        acc_g += __shfl_down_sync(0xFFFFFFFFu, acc_g, o);
    }
    if ((tid & 31) < 2) {                                // lanes 0 and 1 hold 16-lane halves
#pragma unroll
        for (int j = 0; j < W; ++j) {
            const unsigned cp = (unsigned)((acc_p >> (10 * j)) & 1023u);
            const unsigned ci = (unsigned)((acc_i >> (10 * j)) & 1023u);
            const unsigned cg = (unsigned)((acc_g >> (10 * j)) & 1023u);
            if (cp) atomicAdd(&s_pred[j], cp);
            if (ci) atomicAdd(&s_inter[j], ci);
            if (cg) atomicAdd(&s_gt[j], cg);
        }
    }
    __syncthreads();
    if (tid < W) {
        const int g = b * C + start + tid;
        const unsigned sp = s_pred[tid], si = s_inter[tid], sg = s_gt[tid];
        if (sp) atomicAdd(&g_pred[g], sp);
        if (si) atomicAdd(&g_inter[g], si);
        if (sg) atomicAdd(&g_gt[g], sg);
    }
}

__global__ void __launch_bounds__(TPB_F)
seg_hist_cpa(const float* __restrict__ logits,
             const int* __restrict__ targets,
             const int* __restrict__ labels,
             float* __restrict__ pred_out,
             float* __restrict__ mean_out,
             int C, int N, int B, int total_blocks)
{
    __shared__ __align__(16) char sm[DEPTH * ROWS * ROW_B];   // 43008 B
    __shared__ unsigned s_pred[8], s_inter[8], s_gt[8];

    const int tid = threadIdx.x;
    if (tid < 8) { s_pred[tid] = 0u; s_inter[tid] = 0u; s_gt[tid] = 0u; }
    __syncthreads();

    const int b = blockIdx.y;
    int cls = labels[b];
    cls = min(max(cls, 0), 15);
    const int start = c_starts[cls];
    const int width = c_starts[cls + 1] - start;

    const int n0 = blockIdx.x * SPAN;
    const float* l0 = logits + ((size_t)b * C + start) * N + n0;   // stage offsets added inside
    const int* tb = targets + (size_t)b * N + n0;
    float* pb = pred_out + (size_t)b * N;
    const uint32_t sm_a = (uint32_t)__cvta_generic_to_shared(sm);

    switch (width) {
        case 2: fast_body<2>(l0, tb, pb, start, N, b, C, n0, sm, sm_a, s_pred, s_inter, s_gt); break;
        case 3: fast_body<3>(l0, tb, pb, start, N, b, C, n0, sm, sm_a, s_pred, s_inter, s_gt); break;
        case 4: fast_body<4>(l0, tb, pb, start, N, b, C, n0, sm, sm_a, s_pred, s_inter, s_gt); break;
        default: fast_body<6>(l0, tb, pb, start, N, b, C, n0, sm, sm_a, s_pred, s_inter, s_gt); break;
    }

    // ---- last-block finalize (fused tail) ----
    __shared__ unsigned s_last;
    if (tid == 0) {
        __threadfence();
        s_last = (atomicAdd(&g_done, 1u) == (unsigned)(total_blocks - 1)) ? 1u : 0u;
    }
    __syncthreads();
    if (!s_last) return;

    __shared__ float s_iou[64];
    float v = 0.0f;
    if (tid < B) {
        int cl = labels[tid];
        cl = min(max(cl, 0), 15);
        const int st = c_starts[cl];
        const int wd = c_starts[cl + 1] - st;

        unsigned ci[6], cp[6], cg[6];
#pragma unroll
        for (int j = 0; j < 6; ++j) {
            const int g = tid * C + st + min(j, wd - 1);
            ci[j] = g_inter[g]; cp[j] = g_pred[g]; cg[j] = g_gt[g];
        }
        float acc = 0.0f;
#pragma unroll
        for (int j = 0; j < 6; ++j) {
            if (j < wd) {
                const float inter = (float)ci[j];
                const float uni = (float)cp[j] + (float)cg[j] - inter;
                acc += (uni == 0.0f) ? 1.0f : (inter / fmaxf(uni, 1.0f));
            }
        }
        v = acc / (float)wd;
#pragma unroll
        for (int j = 0; j < 6; ++j) {
            if (j < wd) {
                const int g = tid * C + st + j;
                g_inter[g] = 0u; g_pred[g] = 0u; g_gt[g] = 0u;   // reset for next replay
            }
        }
    }
    if (tid < 64) s_iou[tid] = v;
    __syncthreads();
    if (tid == 0) {
        float total = 0.0f;
        for (int i = 0; i < B; i++) total += s_iou[i];
        if (mean_out) *mean_out = total / (float)B;
        g_done = 0u;
        __threadfence();
    }
}

// ---------------- fallback (generic sizes): separate kernels ----------------
template <int TPB>
__global__ void __launch_bounds__(TPB)
seg_hist_generic(const float* __restrict__ logits,
                 const int* __restrict__ targets,
                 const int* __restrict__ labels,
                 float* __restrict__ pred_out,
                 int C, int N)
{
    const int b = blockIdx.y;
    int cls = labels[b];
    cls = min(max(cls, 0), 15);
    const int start = c_starts[cls];
    const int width = c_starts[cls + 1] - start;

    __shared__ unsigned s_pred[8], s_gt[8], s_inter[8];
    if (threadIdx.x < 8) { s_pred[threadIdx.x] = 0u; s_gt[threadIdx.x] = 0u; s_inter[threadIdx.x] = 0u; }
    __syncthreads();

    const float* lb = logits + (size_t)b * C * N;
    const int* tb = targets + (size_t)b * N;
    float* pb = pred_out + (size_t)b * N;

    const int pts = (N + gridDim.x - 1) / gridDim.x;
    const int n0 = blockIdx.x * pts;
    const int n1 = min(n0 + pts, N);

    for (int n = n0 + threadIdx.x; n < n1; n += TPB) {
        float best = lb[(size_t)start * N + n];
        int bestc = 0;
        for (int j = 1; j < width; j++) {
            float v = lb[(size_t)(start + j) * N + n];
            if (v > best) { best = v; bestc = j; }
        }
        const unsigned bt = (unsigned)(tb[n] - start);
        atomicAdd(&s_pred[bestc], 1u);
        if (bt == (unsigned)bestc) atomicAdd(&s_inter[bestc], 1u);
        if (bt < (unsigned)width) atomicAdd(&s_gt[bt], 1u);
        pb[n] = (float)(bestc + start);
    }
    __syncthreads();
    if (threadIdx.x < width) {
        const int g = b * C + start + threadIdx.x;
        if (s_pred[threadIdx.x])  atomicAdd(&g_pred[g],  s_pred[threadIdx.x]);
        if (s_gt[threadIdx.x])    atomicAdd(&g_gt[g],    s_gt[threadIdx.x]);
        if (s_inter[threadIdx.x]) atomicAdd(&g_inter[g], s_inter[threadIdx.x]);
    }
}

__global__ void finalize_kernel(const int* __restrict__ labels,
                                float* __restrict__ mean_out,
                                int B, int C)
{
    __shared__ float s_iou[128];
    const int b = threadIdx.x;
    float v = 0.0f;
    if (b < B) {
        int cls = labels[b];
        cls = min(max(cls, 0), 15);
        const int start = c_starts[cls];
        const int end = c_starts[cls + 1];
        float acc = 0.0f;
        for (int p = start; p < end; p++) {
            const int g = b * C + p;
            const float inter = (float)g_inter[g];
            const float uni = (float)g_pred[g] + (float)g_gt[g] - inter;
            const float iou = (uni == 0.0f) ? 1.0f : (inter / fmaxf(uni, 1.0f));
            acc += iou;
            g_inter[g] = 0u; g_pred[g] = 0u; g_gt[g] = 0u;
        }
        v = acc / (float)(end - start);
    }
    if (b < 128) s_iou[b] = v;
    __syncthreads();
    if (threadIdx.x == 0) {
        float total = 0.0f;
        for (int i = 0; i < B; i++) total += s_iou[i];
        if (mean_out) *mean_out = total / (float)B;
    }
}

extern "C" void kernel_launch(void* const* d_in, const int* in_sizes, int n_in,
                              void* d_out, int out_size)
{
    // Identify inputs by element count (labels: B, targets: B*N, logits: B*C*N)
    int i_log = 0, i_lab = 0;
    for (int i = 0; i < 3; i++) {
        if (in_sizes[i] > in_sizes[i_log]) i_log = i;
        if (in_sizes[i] < in_sizes[i_lab]) i_lab = i;
    }
    const int i_tgt = 3 - i_log - i_lab;

    const float* logits  = (const float*)d_in[i_log];
    const int*   targets = (const int*)d_in[i_tgt];
    const int*   labels  = (const int*)d_in[i_lab];

    const int B  = in_sizes[i_lab];
    const int BN = in_sizes[i_tgt];
    const int N  = BN / B;
    const int C  = in_sizes[i_log] / BN;

    float* out = (float*)d_out;
    float* mean_out = nullptr;
    float* pred_out = nullptr;
    if (out_size >= BN + 1)      { mean_out = out; pred_out = out + 1; }
    else if (out_size == BN)     { pred_out = out; }
    else                         { mean_out = out; pred_out = out; }

    if (pred_out && (N % SPAN) == 0 && B <= 64 && B * C <= MAX_BC) {
        dim3 grid(N / SPAN, B);
        const int total_blocks = (N / SPAN) * B;
        seg_hist_cpa<<<grid, TPB_F>>>(logits, targets, labels, pred_out,
                                      mean_out, C, N, B, total_blocks);
    } else {
        dim3 grid(32, B);
        seg_hist_generic<256><<<grid, 256>>>(logits, targets, labels, pred_out, C, N);
        finalize_kernel<<<1, 128>>>(labels, mean_out, B, C);
    }
}